// round 12
// baseline (speedup 1.0000x reference)
#include <cuda_runtime.h>

// ---------------- problem constants ----------------
#define GXc   352
#define GYc   400
#define GXY   140800            // GXc*GYc
#define NPTS  262144            // 4 * 65536
#define SENT  563200            // 4*GXY  (sentinel id)
#define NSEG  563201            // SENT+1
#define OC    64
#define TP    256               // points per tile
#define NMOM  104               // 13 sums + 91 upper-triangular products
#define ABLKB 256               // assign blocks (1024 thr): 256*1024 == NPTS
#define SCANB 550               // scan blocks (1024 thr): 550*1024 == SENT
#define SBLK  1024              // scatter blocks (NPTS / TP)
#define NFIN4 (NSEG * 16)       // float4 elements in feat region = 9,011,216
#define FINB  2201              // finalize blocks (1024 thr, 4x unroll)
#define MBLK  296               // moments blocks (2 per SM)

// ---------------- device scratch (static, no allocs) ----------------
struct Scratch {                         // zeroed by ONE memset node
    float4 sumc[NSEG];                   // per-pillar sum x,y,z + count
    double mom[NMOM];                    // feature moments (S1[13], M2 upper[91])
    int    cnt_assign;                   // assign-role arrival counter
    int    cnt_scan;                     // scan-aggregate arrival counter
    int    cnt_mom;                      // moments arrival counter
};
__device__ Scratch g_scr;
__device__ float  g_scale[OC], g_shift[OC];
__device__ int    g_intra[SENT];         // intra-block exclusive scan of occupancy
__device__ int    g_bsum[SCANB];
__device__ int    g_boff[SCANB];
__device__ int    g_total;

// ---------------- pillar id (must match jax fp32 bit-exactly) ----------------
__device__ __forceinline__ int point_lin(float x, float y, float z, int i,
                                         int* pcx, int* pcy, int* pcz, bool* pm) {
    float cfx = __fdiv_rn(x, 0.2f);            // (x - 0)   / 0.2
    float cfy = __fdiv_rn(y + 40.0f, 0.2f);    // (y + 40)  / 0.2
    float cfz = __fdiv_rn(z + 3.0f, 4.0f);     // (z + 3)   / 4
    int cx = (int)cfx, cy = (int)cfy, cz = (int)cfz;  // trunc == astype(int32)
    bool m = (cfx >= 0.f) && (cfx < 352.f) && (cfy >= 0.f) && (cfy < 400.f);
    *pcx = cx; *pcy = cy; *pcz = cz; *pm = m;
    return m ? ((i >> 16) * GXY + cx * GYc + cy) : SENT;
}

// ---------------- f32x2 helpers ----------------
__device__ __forceinline__ unsigned long long pack2(float a, float b) {
    unsigned long long r;
    asm("mov.b64 %0, {%1, %2};" : "=l"(r) : "f"(a), "f"(b));
    return r;
}
__device__ __forceinline__ void ffma2_dup(unsigned long long& acc, float f,
                                          unsigned long long w) {
    unsigned long long fd;
    asm("mov.b64 %0, {%1, %1};" : "=l"(fd) : "f"(f));          // alu pipe
    asm("fma.rn.f32x2 %0, %1, %2, %0;" : "+l"(acc) : "l"(fd), "l"(w)); // fma pipe
}

// ------ phase1: assign role (vector RED) + scan role (spin, L2-hot) ---------
__global__ void k_phase1(const float* __restrict__ pts) {
    int bi = blockIdx.x;
    int t = threadIdx.x, lane = t & 31, w = t >> 5;

    if (bi < ABLKB) {
        // ------- assign role -------
        int i = bi * 1024 + t;
        const float* p = pts + (size_t)i * 7;
        float x = p[0], y = p[1], z = p[2];
        int cx, cy, cz; bool m;
        int lin = point_lin(x, y, z, i, &cx, &cy, &cz, &m);
        float4* s = &g_scr.sumc[lin];
        asm volatile("red.global.add.v4.f32 [%0], {%1, %2, %3, %4};"
                     :: "l"(s), "f"(x), "f"(y), "f"(z), "f"(1.0f) : "memory");
        __threadfence();
        __syncthreads();
        if (t == 0) atomicAdd(&g_scr.cnt_assign, 1);
        return;
    }

    // ------- scan role: wait for all assign blocks, then scan occupancy -----
    if (t == 0) {
        volatile int* c = &g_scr.cnt_assign;
        while (*c < ABLKB) __nanosleep(64);
    }
    __syncthreads();
    __threadfence();

    __shared__ int ws[32];
    __shared__ int isLast;
    int sb = bi - ABLKB;
    int cell = sb * 1024 + t;                  // 550*1024 == SENT exactly
    int occ = (__ldcg(&g_scr.sumc[cell].w) > 0.f) ? 1 : 0;
    unsigned bal = __ballot_sync(0xffffffffu, occ);
    int wex = __popc(bal & ((1u << lane) - 1u));   // exclusive within warp
    if (lane == 31) ws[w] = wex + occ;             // warp total
    __syncthreads();
    if (w == 0) {
        int v = ws[lane];
        int s = v;
        #pragma unroll
        for (int o = 1; o < 32; o <<= 1) {
            int xv = __shfl_up_sync(0xffffffffu, s, o);
            if (lane >= o) s += xv;
        }
        ws[lane] = s - v;                          // exclusive warp offsets
        if (lane == 31) g_bsum[sb] = s;            // block total (aggregate)
    }
    __syncthreads();
    g_intra[cell] = ws[w] + wex;

    __threadfence();
    if (t == 0) {
        int old = atomicAdd(&g_scr.cnt_scan, 1);
        isLast = (old == SCANB - 1);
    }
    __syncthreads();
    if (!isLast) return;
    __threadfence();

    int v = (t < SCANB) ? __ldcg(&g_bsum[t]) : 0;
    int s = v;
    #pragma unroll
    for (int o = 1; o < 32; o <<= 1) {
        int xv = __shfl_up_sync(0xffffffffu, s, o);
        if (lane >= o) s += xv;
    }
    if (lane == 31) ws[w] = s;
    __syncthreads();
    if (w == 0) {
        int v2 = ws[lane];
        int s2 = v2;
        #pragma unroll
        for (int o = 1; o < 32; o <<= 1) {
            int xv = __shfl_up_sync(0xffffffffu, s2, o);
            if (lane >= o) s2 += xv;
        }
        ws[lane] = s2 - v2;                        // exclusive across warps
    }
    __syncthreads();
    int excl = ws[w] + s - v;
    if (t < SCANB) g_boff[t] = excl;
    if (t == SCANB - 1) g_total = excl + v;
}

// ------- feature moments + (last block) BN scale/shift fold -----------------
__device__ __forceinline__ void mom_point(const float* __restrict__ pts, int i,
                                          float* acc) {
    const float* p = pts + (size_t)i * 7;
    float x = p[0], y = p[1], z = p[2];
    int cx, cy, cz; bool m;
    int lin = point_lin(x, y, z, i, &cx, &cy, &cz, &m);
    float4 sc = g_scr.sumc[lin];
    float cnt = fmaxf(sc.w, 1.f);
    float f[13];
    f[0] = x; f[1] = y; f[2] = z;
    f[3] = p[3]; f[4] = p[4]; f[5] = p[5]; f[6] = p[6];
    f[7] = x - __fdiv_rn(sc.x, cnt);
    f[8] = y - __fdiv_rn(sc.y, cnt);
    f[9] = z - __fdiv_rn(sc.z, cnt);
    f[10] = x - ((float)cx * 0.2f + 0.1f);
    f[11] = y - ((float)cy * 0.2f + 0.1f - 40.0f);
    f[12] = z - ((float)cz * 4.0f + 2.0f - 3.0f);
    int idx = 13;
    #pragma unroll
    for (int k = 0; k < 13; k++) acc[k] += f[k];
    #pragma unroll
    for (int k = 0; k < 13; k++)
        #pragma unroll
        for (int l = k; l < 13; l++) acc[idx++] += f[k] * f[l];
}

__global__ void k_moments(const float* __restrict__ pts,
                          const float* __restrict__ W,
                          const float* __restrict__ gamma,
                          const float* __restrict__ beta) {
    float acc[NMOM];
    #pragma unroll
    for (int k = 0; k < NMOM; k++) acc[k] = 0.f;

    const int stride = MBLK * 256;
    int i = blockIdx.x * 256 + threadIdx.x;
    for (; i + stride < NPTS; i += 2 * stride) {     // unroll 2: MLP on gathers
        mom_point(pts, i, acc);
        mom_point(pts, i + stride, acc);
    }
    if (i < NPTS) mom_point(pts, i, acc);

    #pragma unroll
    for (int k = 0; k < NMOM; k++) {
        float v = acc[k];
        v += __shfl_down_sync(0xffffffffu, v, 16);
        v += __shfl_down_sync(0xffffffffu, v, 8);
        v += __shfl_down_sync(0xffffffffu, v, 4);
        v += __shfl_down_sync(0xffffffffu, v, 2);
        v += __shfl_down_sync(0xffffffffu, v, 1);
        acc[k] = v;
    }
    __shared__ float part[8][NMOM];
    __shared__ int isLast;
    int lane = threadIdx.x & 31, w = threadIdx.x >> 5;
    if (lane == 0) {
        #pragma unroll
        for (int k = 0; k < NMOM; k++) part[w][k] = acc[k];
    }
    __syncthreads();
    int t = threadIdx.x;
    if (t < NMOM) {
        double s = 0.0;
        #pragma unroll
        for (int ww = 0; ww < 8; ww++) s += (double)part[ww][t];
        atomicAdd(&g_scr.mom[t], s);
    }

    // last block folds BN scale/shift (runs exactly once)
    __threadfence();
    if (t == 0) {
        int old = atomicAdd(&g_scr.cnt_mom, 1);
        isLast = (old == MBLK - 1);
    }
    __syncthreads();
    if (!isLast) return;
    __threadfence();

    if (t < OC) {
        double wv[13];
        const float* wr = W + t * 13;
        #pragma unroll
        for (int k = 0; k < 13; k++) wv[k] = (double)__ldg(wr + k);
        double s1 = 0.0;
        #pragma unroll
        for (int k = 0; k < 13; k++) s1 += wv[k] * __ldcg(&g_scr.mom[k]);
        const double n = (double)NPTS;
        double mu = s1 / n;
        double q0 = 0.0, q1 = 0.0, q2 = 0.0, q3 = 0.0;
        int idx = 13;
        #pragma unroll
        for (int k = 0; k < 13; k++)
            #pragma unroll
            for (int l = k; l < 13; l++) {
                double term = wv[k] * wv[l] * __ldcg(&g_scr.mom[idx]);
                if (l != k) term += term;
                switch (idx & 3) {
                    case 0: q0 += term; break;
                    case 1: q1 += term; break;
                    case 2: q2 += term; break;
                    default: q3 += term; break;
                }
                idx++;
            }
        double var = (q0 + q1 + q2 + q3) / n - mu * mu;
        double inv = rsqrt(var + 1e-3);
        double s = (double)__ldg(gamma + t) * inv;
        g_scale[t] = (float)s;
        g_shift[t] = (float)((double)__ldg(beta + t) - mu * s);
    }
}

// ------ scatter: warp=point, lane=2ch, FFMA2; PDL primary for k_fin ---------
__global__ void __launch_bounds__(256) k_scatter(const float* __restrict__ pts,
                                                 const float* __restrict__ W,
                                                 float* __restrict__ outF) {
    // fire PDL trigger ASAP: k_fin (independent of this kernel's outputs)
    // launches and overlaps the whole scatter phase.
    cudaTriggerProgrammaticLaunchCompletion();

    __shared__ float sF[TP][16];          // 13 feats padded to 16
    __shared__ float sW[13][OC];          // W transposed
    __shared__ int   sRank[TP];           // (rank<<1)|single, or -1

    int t = threadIdx.x;
    int bi = blockIdx.x;
    for (int idx = t; idx < 13 * OC; idx += 256) {
        int k = idx >> 6, c = idx & 63;
        sW[k][c] = W[c * 13 + k];
    }

    // phase 1: one thread per point -> feats to shared
    int i = bi * TP + t;
    const float* p = pts + (size_t)i * 7;
    float x = p[0], y = p[1], z = p[2];
    float r3 = p[3], r4 = p[4], r5 = p[5], r6 = p[6];
    int cx, cy, cz; bool m;
    int lin = point_lin(x, y, z, i, &cx, &cy, &cz, &m);
    float4 sc = g_scr.sumc[lin];
    float cnt = fmaxf(sc.w, 1.f);
    sF[t][0] = x;  sF[t][1] = y;  sF[t][2] = z;
    sF[t][3] = r3; sF[t][4] = r4; sF[t][5] = r5; sF[t][6] = r6;
    sF[t][7] = x - __fdiv_rn(sc.x, cnt);
    sF[t][8] = y - __fdiv_rn(sc.y, cnt);
    sF[t][9] = z - __fdiv_rn(sc.z, cnt);
    sF[t][10] = x - ((float)cx * 0.2f + 0.1f);
    sF[t][11] = y - ((float)cy * 0.2f + 0.1f - 40.0f);
    sF[t][12] = z - ((float)cz * 4.0f + 2.0f - 3.0f);
    sF[t][13] = 0.f; sF[t][14] = 0.f; sF[t][15] = 0.f;
    sRank[t] = m ? (((g_intra[lin] + g_boff[lin >> 10]) << 1) | (sc.w == 1.0f))
                 : -1;
    __syncthreads();

    // phase 2: warp = one point per iteration, lane = channels (2l, 2l+1)
    int lane = t & 31, wp = t >> 5;
    unsigned long long wp2[13];
    #pragma unroll
    for (int k = 0; k < 13; k++)
        wp2[k] = pack2(sW[k][2 * lane], sW[k][2 * lane + 1]);
    unsigned long long scp = pack2(g_scale[2 * lane], g_scale[2 * lane + 1]);
    unsigned long long shp = pack2(g_shift[2 * lane], g_shift[2 * lane + 1]);

    for (int pp = wp; pp < TP; pp += 8) {
        int v = sRank[pp];
        if (v < 0) continue;
        const float4* fr = (const float4*)sF[pp];
        float4 a = fr[0], b = fr[1], cc = fr[2], d = fr[3];
        unsigned long long acc = 0ULL;             // {0.f, 0.f}
        ffma2_dup(acc, a.x,  wp2[0]);
        ffma2_dup(acc, a.y,  wp2[1]);
        ffma2_dup(acc, a.z,  wp2[2]);
        ffma2_dup(acc, a.w,  wp2[3]);
        ffma2_dup(acc, b.x,  wp2[4]);
        ffma2_dup(acc, b.y,  wp2[5]);
        ffma2_dup(acc, b.z,  wp2[6]);
        ffma2_dup(acc, b.w,  wp2[7]);
        ffma2_dup(acc, cc.x, wp2[8]);
        ffma2_dup(acc, cc.y, wp2[9]);
        ffma2_dup(acc, cc.z, wp2[10]);
        ffma2_dup(acc, cc.w, wp2[11]);
        ffma2_dup(acc, d.x,  wp2[12]);
        // BN fold: y = acc*scale + shift (packed), then relu per half
        asm("fma.rn.f32x2 %0, %0, %1, %2;" : "+l"(acc) : "l"(scp), "l"(shp));
        float yA, yB;
        asm("mov.b64 {%0, %1}, %2;" : "=f"(yA), "=f"(yB) : "l"(acc));
        yA = fmaxf(yA, 0.f);
        yB = fmaxf(yB, 0.f);
        float* dst = outF + (size_t)(v >> 1) * OC + 2 * lane;
        if (v & 1) {
            *(float2*)dst = make_float2(yA, yB);   // sole point of its pillar
        } else {
            // signed-int max: y >= 0 beats stale 0 / other points, idempotent
            atomicMax((int*)dst,     __float_as_int(yA));
            atomicMax((int*)dst + 1, __float_as_int(yB));
        }
    }
}

// ------ finalize: tail zero + coords + grid (PDL: overlaps k_scatter) -------
// Reads ONLY phase1 outputs and writes rows >= g_total + coords — fully
// disjoint from k_scatter's writes (rows < g_total), so no
// cudaGridDependencySynchronize is needed.
__global__ void k_fin(float* __restrict__ outF,
                      float* __restrict__ outC,
                      float* __restrict__ outG) {
    int fid = blockIdx.x;
    int t = threadIdx.x;
    int total = g_total;
    float4 z4 = make_float4(0.f, 0.f, 0.f, 0.f);
    #pragma unroll
    for (int k = 0; k < 4; k++) {
        int vt = fid * 4096 + k * 1024 + t;
        // tail feature rows -> 0 (16 float4 per row)
        if (vt < NFIN4 && (vt >> 4) >= total)
            ((float4*)outF)[vt] = z4;
        if (outC) {
            if (vt < SENT && g_scr.sumc[vt].w > 0.f) {
                int j = g_intra[vt] + g_boff[vt >> 10];
                int b = vt / GXY;
                int rem = vt % GXY;
                int cx = rem / GYc;
                int cy = rem % GYc;
                float* o = outC + (size_t)j * 3;
                o[0] = (float)b; o[1] = (float)cy; o[2] = (float)cx;
            }
            if (vt < NSEG && vt >= total) {
                float* o = outC + (size_t)vt * 3;
                o[0] = 4.f; o[1] = 0.f; o[2] = 0.f;   // sentinel -> (4,0,0)
            }
        }
    }
    if (fid == 0 && t == 0 && outG) { outG[0] = 400.f; outG[1] = 352.f; }
}

// ---------------- launch ----------------
extern "C" void kernel_launch(void* const* d_in, const int* in_sizes, int n_in,
                              void* d_out, int out_size) {
    const float* pts   = (const float*)d_in[0];
    const float* W     = (const float*)d_in[1];
    const float* gamma = (const float*)d_in[2];
    const float* beta  = (const float*)d_in[3];

    float* outF = (float*)d_out;
    const size_t featN = (size_t)NSEG * OC;            // 36,044,864
    float* outC = outF + featN;
    float* outG = outC + (size_t)NSEG * 3;
    bool haveC = (size_t)out_size >= featN + (size_t)NSEG * 3;
    bool haveG = (size_t)out_size >= featN + (size_t)NSEG * 3 + 2;

    void* p_scr = nullptr;
    cudaGetSymbolAddress(&p_scr, g_scr);
    cudaMemsetAsync(p_scr, 0, sizeof(Scratch));        // one node zeroes all

    k_phase1<<<ABLKB + SCANB, 1024>>>(pts);
    k_moments<<<MBLK, 256>>>(pts, W, gamma, beta);

    // scatter (primary): triggers PDL at entry -> k_fin overlaps it.
    k_scatter<<<SBLK, 256>>>(pts, W, outF);

    // k_fin (dependent): launches while scatter runs; writes only tail rows
    // and coords (disjoint from scatter's rows), reads only phase1 outputs.
    {
        cudaLaunchConfig_t cfg = {};
        cfg.gridDim  = dim3(FINB, 1, 1);
        cfg.blockDim = dim3(1024, 1, 1);
        cfg.dynamicSmemBytes = 0;
        cfg.stream = 0;
        cudaLaunchAttribute attr[1];
        attr[0].id = cudaLaunchAttributeProgrammaticStreamSerialization;
        attr[0].val.programmaticStreamSerializationAllowed = 1;
        cfg.attrs = attr;
        cfg.numAttrs = 1;
        float* c = haveC ? outC : nullptr;
        float* g = haveG ? outG : nullptr;
        cudaLaunchKernelEx(&cfg, k_fin, outF, c, g);
    }
}

// round 13
// speedup vs baseline: 1.2984x; 1.2984x over previous
#include <cuda_runtime.h>

// ---------------- problem constants ----------------
#define GXc   352
#define GYc   400
#define GXY   140800            // GXc*GYc
#define NPTS  262144            // 4 * 65536
#define SENT  563200            // 4*GXY  (sentinel id)
#define NSEG  563201            // SENT+1
#define OC    64
#define TP    256               // points per tile
#define NMOM  104               // 13 sums + 91 upper-triangular products
#define ABLKB 256               // assign blocks (1024 thr): 256*1024 == NPTS
#define SCANB 550               // scan blocks (1024 thr): 550*1024 == SENT
#define SBLK  1024              // scatter blocks (NPTS / TP)
#define NFIN4 (NSEG * 16)       // float4 elements in feat region = 9,011,216
#define ZROLE 1408              // dense tail-zero blocks in k_fin
#define CROLE 551               // coords blocks in k_fin (551*1024 >= NSEG)
#define MBLK  296               // moments blocks (2 per SM)

// ---------------- device scratch (static, no allocs) ----------------
struct Scratch {                         // zeroed by ONE memset node
    float4 sumc[NSEG];                   // per-pillar sum x,y,z + count
    double mom[NMOM];                    // feature moments (S1[13], M2 upper[91])
    int    cnt_assign;                   // assign-role arrival counter
    int    cnt_scan;                     // scan-aggregate arrival counter
    int    cnt_mom;                      // moments arrival counter
};
__device__ Scratch g_scr;
__device__ float  g_scale[OC], g_shift[OC];
__device__ int    g_intra[SENT];         // intra-block exclusive scan of occupancy
__device__ int    g_bsum[SCANB];
__device__ int    g_boff[SCANB];
__device__ int    g_total;

// ---------------- pillar id (must match jax fp32 bit-exactly) ----------------
__device__ __forceinline__ int point_lin(float x, float y, float z, int i,
                                         int* pcx, int* pcy, int* pcz, bool* pm) {
    float cfx = __fdiv_rn(x, 0.2f);            // (x - 0)   / 0.2
    float cfy = __fdiv_rn(y + 40.0f, 0.2f);    // (y + 40)  / 0.2
    float cfz = __fdiv_rn(z + 3.0f, 4.0f);     // (z + 3)   / 4
    int cx = (int)cfx, cy = (int)cfy, cz = (int)cfz;  // trunc == astype(int32)
    bool m = (cfx >= 0.f) && (cfx < 352.f) && (cfy >= 0.f) && (cfy < 400.f);
    *pcx = cx; *pcy = cy; *pcz = cz; *pm = m;
    return m ? ((i >> 16) * GXY + cx * GYc + cy) : SENT;
}

// ---------------- f32x2 helpers ----------------
__device__ __forceinline__ unsigned long long pack2(float a, float b) {
    unsigned long long r;
    asm("mov.b64 %0, {%1, %2};" : "=l"(r) : "f"(a), "f"(b));
    return r;
}
__device__ __forceinline__ void ffma2_dup(unsigned long long& acc, float f,
                                          unsigned long long w) {
    unsigned long long fd;
    asm("mov.b64 %0, {%1, %1};" : "=l"(fd) : "f"(f));          // alu pipe
    asm("fma.rn.f32x2 %0, %1, %2, %0;" : "+l"(acc) : "l"(fd), "l"(w)); // fma pipe
}

// ------ phase1: assign role (vector RED) + scan role (spin, L2-hot) ---------
__global__ void k_phase1(const float* __restrict__ pts) {
    int bi = blockIdx.x;
    int t = threadIdx.x, lane = t & 31, w = t >> 5;

    if (bi < ABLKB) {
        // ------- assign role -------
        int i = bi * 1024 + t;
        const float* p = pts + (size_t)i * 7;
        float x = p[0], y = p[1], z = p[2];
        int cx, cy, cz; bool m;
        int lin = point_lin(x, y, z, i, &cx, &cy, &cz, &m);
        float4* s = &g_scr.sumc[lin];
        asm volatile("red.global.add.v4.f32 [%0], {%1, %2, %3, %4};"
                     :: "l"(s), "f"(x), "f"(y), "f"(z), "f"(1.0f) : "memory");
        __threadfence();
        __syncthreads();
        if (t == 0) atomicAdd(&g_scr.cnt_assign, 1);
        return;
    }

    // ------- scan role: wait for all assign blocks, then scan occupancy -----
    if (t == 0) {
        volatile int* c = &g_scr.cnt_assign;
        while (*c < ABLKB) __nanosleep(64);
    }
    __syncthreads();
    __threadfence();

    __shared__ int ws[32];
    __shared__ int isLast;
    int sb = bi - ABLKB;
    int cell = sb * 1024 + t;                  // 550*1024 == SENT exactly
    int occ = (__ldcg(&g_scr.sumc[cell].w) > 0.f) ? 1 : 0;
    unsigned bal = __ballot_sync(0xffffffffu, occ);
    int wex = __popc(bal & ((1u << lane) - 1u));   // exclusive within warp
    if (lane == 31) ws[w] = wex + occ;             // warp total
    __syncthreads();
    if (w == 0) {
        int v = ws[lane];
        int s = v;
        #pragma unroll
        for (int o = 1; o < 32; o <<= 1) {
            int xv = __shfl_up_sync(0xffffffffu, s, o);
            if (lane >= o) s += xv;
        }
        ws[lane] = s - v;                          // exclusive warp offsets
        if (lane == 31) g_bsum[sb] = s;            // block total (aggregate)
    }
    __syncthreads();
    g_intra[cell] = ws[w] + wex;

    __threadfence();
    if (t == 0) {
        int old = atomicAdd(&g_scr.cnt_scan, 1);
        isLast = (old == SCANB - 1);
    }
    __syncthreads();
    if (!isLast) return;
    __threadfence();

    int v = (t < SCANB) ? __ldcg(&g_bsum[t]) : 0;
    int s = v;
    #pragma unroll
    for (int o = 1; o < 32; o <<= 1) {
        int xv = __shfl_up_sync(0xffffffffu, s, o);
        if (lane >= o) s += xv;
    }
    if (lane == 31) ws[w] = s;
    __syncthreads();
    if (w == 0) {
        int v2 = ws[lane];
        int s2 = v2;
        #pragma unroll
        for (int o = 1; o < 32; o <<= 1) {
            int xv = __shfl_up_sync(0xffffffffu, s2, o);
            if (lane >= o) s2 += xv;
        }
        ws[lane] = s2 - v2;                        // exclusive across warps
    }
    __syncthreads();
    int excl = ws[w] + s - v;
    if (t < SCANB) g_boff[t] = excl;
    if (t == SCANB - 1) g_total = excl + v;
}

// ------- feature moments + (last block) BN scale/shift fold -----------------
__device__ __forceinline__ void mom_point(const float* __restrict__ pts, int i,
                                          float* acc) {
    const float* p = pts + (size_t)i * 7;
    float x = p[0], y = p[1], z = p[2];
    int cx, cy, cz; bool m;
    int lin = point_lin(x, y, z, i, &cx, &cy, &cz, &m);
    float4 sc = g_scr.sumc[lin];
    float cnt = fmaxf(sc.w, 1.f);
    float f[13];
    f[0] = x; f[1] = y; f[2] = z;
    f[3] = p[3]; f[4] = p[4]; f[5] = p[5]; f[6] = p[6];
    f[7] = x - __fdiv_rn(sc.x, cnt);
    f[8] = y - __fdiv_rn(sc.y, cnt);
    f[9] = z - __fdiv_rn(sc.z, cnt);
    f[10] = x - ((float)cx * 0.2f + 0.1f);
    f[11] = y - ((float)cy * 0.2f + 0.1f - 40.0f);
    f[12] = z - ((float)cz * 4.0f + 2.0f - 3.0f);
    int idx = 13;
    #pragma unroll
    for (int k = 0; k < 13; k++) acc[k] += f[k];
    #pragma unroll
    for (int k = 0; k < 13; k++)
        #pragma unroll
        for (int l = k; l < 13; l++) acc[idx++] += f[k] * f[l];
}

__global__ void k_moments(const float* __restrict__ pts,
                          const float* __restrict__ W,
                          const float* __restrict__ gamma,
                          const float* __restrict__ beta) {
    // fire PDL trigger ASAP: lets k_fin launch and overlap with this kernel
    cudaTriggerProgrammaticLaunchCompletion();

    float acc[NMOM];
    #pragma unroll
    for (int k = 0; k < NMOM; k++) acc[k] = 0.f;

    const int stride = MBLK * 256;
    int i = blockIdx.x * 256 + threadIdx.x;
    for (; i + stride < NPTS; i += 2 * stride) {     // unroll 2: MLP on gathers
        mom_point(pts, i, acc);
        mom_point(pts, i + stride, acc);
    }
    if (i < NPTS) mom_point(pts, i, acc);

    #pragma unroll
    for (int k = 0; k < NMOM; k++) {
        float v = acc[k];
        v += __shfl_down_sync(0xffffffffu, v, 16);
        v += __shfl_down_sync(0xffffffffu, v, 8);
        v += __shfl_down_sync(0xffffffffu, v, 4);
        v += __shfl_down_sync(0xffffffffu, v, 2);
        v += __shfl_down_sync(0xffffffffu, v, 1);
        acc[k] = v;
    }
    __shared__ float part[8][NMOM];
    __shared__ int isLast;
    int lane = threadIdx.x & 31, w = threadIdx.x >> 5;
    if (lane == 0) {
        #pragma unroll
        for (int k = 0; k < NMOM; k++) part[w][k] = acc[k];
    }
    __syncthreads();
    int t = threadIdx.x;
    if (t < NMOM) {
        double s = 0.0;
        #pragma unroll
        for (int ww = 0; ww < 8; ww++) s += (double)part[ww][t];
        atomicAdd(&g_scr.mom[t], s);
    }

    // last block folds BN scale/shift (runs exactly once)
    __threadfence();
    if (t == 0) {
        int old = atomicAdd(&g_scr.cnt_mom, 1);
        isLast = (old == MBLK - 1);
    }
    __syncthreads();
    if (!isLast) return;
    __threadfence();

    if (t < OC) {
        double wv[13];
        const float* wr = W + t * 13;
        #pragma unroll
        for (int k = 0; k < 13; k++) wv[k] = (double)__ldg(wr + k);
        double s1 = 0.0;
        #pragma unroll
        for (int k = 0; k < 13; k++) s1 += wv[k] * __ldcg(&g_scr.mom[k]);
        const double n = (double)NPTS;
        double mu = s1 / n;
        double q0 = 0.0, q1 = 0.0, q2 = 0.0, q3 = 0.0;
        int idx = 13;
        #pragma unroll
        for (int k = 0; k < 13; k++)
            #pragma unroll
            for (int l = k; l < 13; l++) {
                double term = wv[k] * wv[l] * __ldcg(&g_scr.mom[idx]);
                if (l != k) term += term;
                switch (idx & 3) {
                    case 0: q0 += term; break;
                    case 1: q1 += term; break;
                    case 2: q2 += term; break;
                    default: q3 += term; break;
                }
                idx++;
            }
        double var = (q0 + q1 + q2 + q3) / n - mu * mu;
        double inv = rsqrt(var + 1e-3);
        double s = (double)__ldg(gamma + t) * inv;
        g_scale[t] = (float)s;
        g_shift[t] = (float)((double)__ldg(beta + t) - mu * s);
    }
}

// ------ finalize (PDL: overlaps k_moments): dense tail-zero + coords --------
// Reads ONLY phase1 outputs (complete before k_moments launched), so no
// cudaGridDependencySynchronize is needed.
__global__ void k_fin(float* __restrict__ outF,
                      float* __restrict__ outC,
                      float* __restrict__ outG) {
    int bi = blockIdx.x;
    int t = threadIdx.x;
    int total = g_total;

    if (bi < ZROLE) {
        // ------- dense tail-zero role: float4 range [total*16, NFIN4) ------
        float4* f4 = (float4*)outF;
        float4 z4 = make_float4(0.f, 0.f, 0.f, 0.f);
        int start = total * 16;
        const int stride = ZROLE * 1024;
        for (int idx = start + bi * 1024 + t; idx < NFIN4; idx += stride)
            f4[idx] = z4;
        return;
    }

    // ------- coords role -------
    if (!outC) return;
    int vt = (bi - ZROLE) * 1024 + t;
    if (vt < SENT && g_scr.sumc[vt].w > 0.f) {
        int j = g_intra[vt] + g_boff[vt >> 10];
        int b = vt / GXY;
        int rem = vt % GXY;
        int cx = rem / GYc;
        int cy = rem % GYc;
        float* o = outC + (size_t)j * 3;
        o[0] = (float)b; o[1] = (float)cy; o[2] = (float)cx;
    }
    if (vt < NSEG && vt >= total) {
        float* o = outC + (size_t)vt * 3;
        o[0] = 4.f; o[1] = 0.f; o[2] = 0.f;        // sentinel -> (4,0,0)
    }
    if (vt == 0 && outG) { outG[0] = 400.f; outG[1] = 352.f; }  // (GY, GX)
}

// ------ scatter: warp=point, lane=2ch, FFMA2 dot products -------------------
__global__ void __launch_bounds__(256) k_scatter(const float* __restrict__ pts,
                                                 const float* __restrict__ W,
                                                 float* __restrict__ outF) {
    __shared__ float sF[TP][16];          // 13 feats padded to 16
    __shared__ float sW[13][OC];          // W transposed
    __shared__ int   sRank[TP];           // (rank<<1)|single, or -1

    int t = threadIdx.x;
    int bi = blockIdx.x;
    for (int idx = t; idx < 13 * OC; idx += 256) {
        int k = idx >> 6, c = idx & 63;
        sW[k][c] = W[c * 13 + k];
    }

    // phase 1: one thread per point -> feats to shared
    int i = bi * TP + t;
    const float* p = pts + (size_t)i * 7;
    float x = p[0], y = p[1], z = p[2];
    float r3 = p[3], r4 = p[4], r5 = p[5], r6 = p[6];
    int cx, cy, cz; bool m;
    int lin = point_lin(x, y, z, i, &cx, &cy, &cz, &m);
    float4 sc = g_scr.sumc[lin];
    float cnt = fmaxf(sc.w, 1.f);
    sF[t][0] = x;  sF[t][1] = y;  sF[t][2] = z;
    sF[t][3] = r3; sF[t][4] = r4; sF[t][5] = r5; sF[t][6] = r6;
    sF[t][7] = x - __fdiv_rn(sc.x, cnt);
    sF[t][8] = y - __fdiv_rn(sc.y, cnt);
    sF[t][9] = z - __fdiv_rn(sc.z, cnt);
    sF[t][10] = x - ((float)cx * 0.2f + 0.1f);
    sF[t][11] = y - ((float)cy * 0.2f + 0.1f - 40.0f);
    sF[t][12] = z - ((float)cz * 4.0f + 2.0f - 3.0f);
    sF[t][13] = 0.f; sF[t][14] = 0.f; sF[t][15] = 0.f;
    sRank[t] = m ? (((g_intra[lin] + g_boff[lin >> 10]) << 1) | (sc.w == 1.0f))
                 : -1;
    __syncthreads();

    // phase 2: warp = one point per iteration, lane = channels (2l, 2l+1)
    int lane = t & 31, wp = t >> 5;
    unsigned long long wp2[13];
    #pragma unroll
    for (int k = 0; k < 13; k++)
        wp2[k] = pack2(sW[k][2 * lane], sW[k][2 * lane + 1]);
    unsigned long long scp = pack2(g_scale[2 * lane], g_scale[2 * lane + 1]);
    unsigned long long shp = pack2(g_shift[2 * lane], g_shift[2 * lane + 1]);

    for (int pp = wp; pp < TP; pp += 8) {
        int v = sRank[pp];
        if (v < 0) continue;
        const float4* fr = (const float4*)sF[pp];
        float4 a = fr[0], b = fr[1], cc = fr[2], d = fr[3];
        unsigned long long acc = 0ULL;             // {0.f, 0.f}
        ffma2_dup(acc, a.x,  wp2[0]);
        ffma2_dup(acc, a.y,  wp2[1]);
        ffma2_dup(acc, a.z,  wp2[2]);
        ffma2_dup(acc, a.w,  wp2[3]);
        ffma2_dup(acc, b.x,  wp2[4]);
        ffma2_dup(acc, b.y,  wp2[5]);
        ffma2_dup(acc, b.z,  wp2[6]);
        ffma2_dup(acc, b.w,  wp2[7]);
        ffma2_dup(acc, cc.x, wp2[8]);
        ffma2_dup(acc, cc.y, wp2[9]);
        ffma2_dup(acc, cc.z, wp2[10]);
        ffma2_dup(acc, cc.w, wp2[11]);
        ffma2_dup(acc, d.x,  wp2[12]);
        // BN fold: y = acc*scale + shift (packed), then relu per half
        asm("fma.rn.f32x2 %0, %0, %1, %2;" : "+l"(acc) : "l"(scp), "l"(shp));
        float yA, yB;
        asm("mov.b64 {%0, %1}, %2;" : "=f"(yA), "=f"(yB) : "l"(acc));
        yA = fmaxf(yA, 0.f);
        yB = fmaxf(yB, 0.f);
        float* dst = outF + (size_t)(v >> 1) * OC + 2 * lane;
        if (v & 1) {
            *(float2*)dst = make_float2(yA, yB);   // sole point of its pillar
        } else {
            // signed-int max: y >= 0 beats stale 0 / other points, idempotent
            atomicMax((int*)dst,     __float_as_int(yA));
            atomicMax((int*)dst + 1, __float_as_int(yB));
        }
    }
}

// ---------------- launch ----------------
extern "C" void kernel_launch(void* const* d_in, const int* in_sizes, int n_in,
                              void* d_out, int out_size) {
    const float* pts   = (const float*)d_in[0];
    const float* W     = (const float*)d_in[1];
    const float* gamma = (const float*)d_in[2];
    const float* beta  = (const float*)d_in[3];

    float* outF = (float*)d_out;
    const size_t featN = (size_t)NSEG * OC;            // 36,044,864
    float* outC = outF + featN;
    float* outG = outC + (size_t)NSEG * 3;
    bool haveC = (size_t)out_size >= featN + (size_t)NSEG * 3;
    bool haveG = (size_t)out_size >= featN + (size_t)NSEG * 3 + 2;

    void* p_scr = nullptr;
    cudaGetSymbolAddress(&p_scr, g_scr);
    cudaMemsetAsync(p_scr, 0, sizeof(Scratch));        // one node zeroes all

    k_phase1<<<ABLKB + SCANB, 1024>>>(pts);

    // k_moments (primary): triggers PDL immediately -> k_fin overlaps it.
    k_moments<<<MBLK, 256>>>(pts, W, gamma, beta);

    // k_fin (dependent): launches once k_moments' blocks are resident;
    // reads only phase1 outputs, so full overlap with k_moments is safe.
    {
        cudaLaunchConfig_t cfg = {};
        cfg.gridDim  = dim3(ZROLE + CROLE, 1, 1);
        cfg.blockDim = dim3(1024, 1, 1);
        cfg.dynamicSmemBytes = 0;
        cfg.stream = 0;
        cudaLaunchAttribute attr[1];
        attr[0].id = cudaLaunchAttributeProgrammaticStreamSerialization;
        attr[0].val.programmaticStreamSerializationAllowed = 1;
        cfg.attrs = attr;
        cfg.numAttrs = 1;
        float* c = haveC ? outC : nullptr;
        float* g = haveG ? outG : nullptr;
        cudaLaunchKernelEx(&cfg, k_fin, outF, c, g);
    }

    k_scatter<<<SBLK, 256>>>(pts, W, outF);            // waits for both
}